// round 13
// baseline (speedup 1.0000x reference)
#include <cuda_runtime.h>
#include <cuda_fp16.h>

// Problem constants
#define Bc   4
#define Vc   5
#define Jc   15
#define Hc   128
#define Wc   240
#define NPTS 128000      // 80*80*20
#define HW   (Hc * Wc)

// One pixel = 16 fp16 joints = 32 bytes, 32B-aligned for LDG.256
struct alignas(32) Pix { uint4 a, b; };

// Transposed fp16 heatmaps: (B*V, H, W) pixels of 16 halves = 19.66 MB
__device__ Pix g_hmT[(size_t)Bc * Vc * HW];

static __device__ __forceinline__ unsigned pack_h2(float lo, float hi) {
    __half2 h = __floats2half2_rn(lo, hi);
    return *reinterpret_cast<unsigned*>(&h);
}

// ---------------------------------------------------------------------------
// Kernel 1: transpose (B,V,J,H,W) f32 -> (B*V, H*W) pixels of 16 f16.
// One thread per pixel: 15 coalesced strided loads, register pack,
// 2 coalesced 128-bit stores. At its ~10us HBM floor.
// ---------------------------------------------------------------------------
__global__ void __launch_bounds__(256) transpose_kernel(const float* __restrict__ hm) {
    const int idx = blockIdx.x * blockDim.x + threadIdx.x;
    if (idx < Bc * Vc * HW) {
        const int bv  = idx / HW;
        const int pix = idx - bv * HW;

        const float* src = hm + (size_t)bv * Jc * HW + pix;
        float v[16];
#pragma unroll
        for (int j = 0; j < Jc; ++j)
            v[j] = __ldg(src + (size_t)j * HW);
        v[15] = 0.0f;

        Pix p;
        p.a.x = pack_h2(v[0],  v[1]);
        p.a.y = pack_h2(v[2],  v[3]);
        p.a.z = pack_h2(v[4],  v[5]);
        p.a.w = pack_h2(v[6],  v[7]);
        p.b.x = pack_h2(v[8],  v[9]);
        p.b.y = pack_h2(v[10], v[11]);
        p.b.z = pack_h2(v[12], v[13]);
        p.b.w = pack_h2(v[14], v[15]);
        g_hmT[idx] = p;
    }
    // PDL: signal the dependent sample_kernel once this CTA's stores are done.
    cudaTriggerProgrammaticLaunchCompletion();
}

// ---------------------------------------------------------------------------
// 256-bit read-only global load (Blackwell LDG.E.256): one full pixel.
// ---------------------------------------------------------------------------
static __device__ __forceinline__ void ldg256(const Pix* p, float (&f)[8]) {
    asm volatile(
        "ld.global.nc.v8.f32 {%0,%1,%2,%3,%4,%5,%6,%7}, [%8];"
        : "=f"(f[0]), "=f"(f[1]), "=f"(f[2]), "=f"(f[3]),
          "=f"(f[4]), "=f"(f[5]), "=f"(f[6]), "=f"(f[7])
        : "l"(p));
}

// Scalar unpack + FMA (proven fastest datapath).
static __device__ __forceinline__ void acc_corner(float (&acc)[16],
                                                  const float (&f)[8], float w) {
#pragma unroll
    for (int i = 0; i < 8; ++i) {
        __half2 h = *reinterpret_cast<const __half2*>(&f[i]);
        float2 u = __half22float2(h);
        acc[2 * i + 0] = fmaf(w, u.x, acc[2 * i + 0]);
        acc[2 * i + 1] = fmaf(w, u.y, acc[2 * i + 1]);
    }
}

// ---------------------------------------------------------------------------
// Kernel 2: gather, lane-QUAD. FOUR threads per (b, n): lane (jx, jy) owns
// corner (x0+jx, y0+jy) and issues exactly ONE LDG.256 per view — the 5
// view-loads are mutually independent (MLP=5/thread). Lanes 2k/2k+1 load
// contiguous 64B so wavefront count is unchanged vs lane-pair. Reduction is
// a 2-round keep-half butterfly (12 shfl); each lane ends with 4 joints.
// ---------------------------------------------------------------------------
__global__ void __launch_bounds__(256, 5) sample_kernel(const float* __restrict__ grid,
                                                        float* __restrict__ out) {
    const int tid = blockIdx.x * blockDim.x + threadIdx.x;  // 0 .. 4*B*NPTS-1
    const int pid = tid >> 2;          // point id
    const int jx  = tid & 1;           // x-corner bit
    const int jy  = (tid >> 1) & 1;    // y-corner bit
    const int b   = pid / NPTS;
    const int n   = pid - b * NPTS;

    // PDL prologue: grid coords do NOT depend on the transpose — load them
    // before the dependency sync so these LDGs overlap the transpose kernel.
    const float2* g2 = reinterpret_cast<const float2*>(grid);
    float2 g[Vc];
#pragma unroll
    for (int v = 0; v < Vc; ++v)
        g[v] = g2[(size_t)(b * Vc + v) * NPTS + n];

    cudaGridDependencySynchronize();

    float acc[16];
#pragma unroll
    for (int i = 0; i < 16; ++i) acc[i] = 0.0f;

#pragma unroll
    for (int v = 0; v < Vc; ++v) {
        const float ix = (g[v].x + 1.0f) * 0.5f * (float)(Wc - 1);
        const float iy = (g[v].y + 1.0f) * 0.5f * (float)(Hc - 1);
        const float x0f = floorf(ix);
        const float y0f = floorf(iy);
        const float wx1 = ix - x0f;      // in [0,1); grid is in [-1,1] so
        const float wy1 = iy - y0f;      // ix,iy are always in-range

        int x0 = (int)x0f;
        int y0 = (int)y0f;
        x0 = max(0, min(x0, Wc - 1));
        y0 = max(0, min(y0, Hc - 1));
        const int xc = min(x0 + jx, Wc - 1);
        const int yc = min(y0 + jy, Hc - 1);

        // this lane's corner weight (clamped corner => its weight is 0)
        const float wx = jx ? wx1 : (1.0f - wx1);
        const float wy = jy ? wy1 : (1.0f - wy1);
        const float w  = wx * wy;

        const Pix* base = g_hmT + (size_t)(b * Vc + v) * HW;

        float f[8];
        ldg256(base + (size_t)yc * Wc + xc, f);
        acc_corner(acc, f, w);
    }

    // Butterfly reduction over the quad, keeping half the joints per round.
    // Round 1 (xor 1, x-partner): keep joints [jx*8, jx*8+8).
    float r8[8];
#pragma unroll
    for (int i = 0; i < 8; ++i) {
        const float send = jx ? acc[i] : acc[i + 8];
        const float keep = jx ? acc[i + 8] : acc[i];
        r8[i] = keep + __shfl_xor_sync(0xffffffffu, send, 1);
    }
    // Round 2 (xor 2, y-partner): keep joints [jbase, jbase+4).
    float r4[4];
#pragma unroll
    for (int i = 0; i < 4; ++i) {
        const float send = jy ? r8[i] : r8[i + 4];
        const float keep = jy ? r8[i + 4] : r8[i];
        r4[i] = keep + __shfl_xor_sync(0xffffffffu, send, 2);
    }

    const int jbase = jx * 8 + jy * 4;
    const float s = 1.0f / (float)Vc;
    float* op = out + (size_t)b * Jc * NPTS + n;
#pragma unroll
    for (int k = 0; k < 4; ++k) {
        if (jbase + k < Jc) {
            float val = r4[k] * s;
            val = fminf(fmaxf(val, 0.0f), 1.0f);
            op[(size_t)(jbase + k) * NPTS] = val;
        }
    }
}

// ---------------------------------------------------------------------------
extern "C" void kernel_launch(void* const* d_in, const int* in_sizes, int n_in,
                              void* d_out, int out_size) {
    const float* heatmaps = (const float*)d_in[0];  // (4,5,15,128,240) f32
    const float* grid     = (const float*)d_in[1];  // (4,5,1,128000,2) f32
    float* out            = (float*)d_out;          // (4,15,80,80,20) f32

    (void)in_sizes; (void)n_in; (void)out_size;

    const int tp_total = Bc * Vc * HW;              // 614400
    transpose_kernel<<<(tp_total + 255) / 256, 256>>>(heatmaps);

    // Sample kernel as a programmatic dependent launch: its grid-load
    // prologue overlaps the transpose; cudaGridDependencySynchronize()
    // inside the kernel enforces ordering before g_hmT is read.
    const int total = Bc * NPTS * 4;                // 2,048,000
    cudaLaunchConfig_t cfg = {};
    cfg.gridDim  = dim3((total + 255) / 256);
    cfg.blockDim = dim3(256);
    cfg.dynamicSmemBytes = 0;
    cudaLaunchAttribute attr[1];
    attr[0].id = cudaLaunchAttributeProgrammaticStreamSerialization;
    attr[0].val.programmaticStreamSerializationAllowed = 1;
    cfg.attrs = attr;
    cfg.numAttrs = 1;
    cudaLaunchKernelEx(&cfg, sample_kernel, grid, out);
}

// round 15
// speedup vs baseline: 1.1806x; 1.1806x over previous
#include <cuda_runtime.h>
#include <cuda_fp16.h>

// Problem constants
#define Bc   4
#define Vc   5
#define Jc   15
#define Hc   128
#define Wc   240
#define NPTS 128000      // 80*80*20
#define HW   (Hc * Wc)

// One pixel = 16 fp16 joints = 32 bytes, 32B-aligned for LDG.256
struct alignas(32) Pix { uint4 a, b; };

// Transposed fp16 heatmaps: (B*V, H, W) pixels of 16 halves = 19.66 MB
__device__ Pix g_hmT[(size_t)Bc * Vc * HW];

static __device__ __forceinline__ unsigned pack_h2(float lo, float hi) {
    __half2 h = __floats2half2_rn(lo, hi);
    return *reinterpret_cast<unsigned*>(&h);
}

// ---------------------------------------------------------------------------
// Kernel 1: transpose (B,V,J,H,W) f32 -> (B*V, H*W) pixels of 16 f16.
// One thread per pixel: 15 coalesced strided loads, register pack,
// 2 coalesced 128-bit stores. At its ~10us HBM floor.
// ---------------------------------------------------------------------------
__global__ void __launch_bounds__(256) transpose_kernel(const float* __restrict__ hm) {
    const int idx = blockIdx.x * blockDim.x + threadIdx.x;
    if (idx < Bc * Vc * HW) {
        const int bv  = idx / HW;
        const int pix = idx - bv * HW;

        const float* src = hm + (size_t)bv * Jc * HW + pix;
        float v[16];
#pragma unroll
        for (int j = 0; j < Jc; ++j)
            v[j] = __ldg(src + (size_t)j * HW);
        v[15] = 0.0f;

        Pix p;
        p.a.x = pack_h2(v[0],  v[1]);
        p.a.y = pack_h2(v[2],  v[3]);
        p.a.z = pack_h2(v[4],  v[5]);
        p.a.w = pack_h2(v[6],  v[7]);
        p.b.x = pack_h2(v[8],  v[9]);
        p.b.y = pack_h2(v[10], v[11]);
        p.b.z = pack_h2(v[12], v[13]);
        p.b.w = pack_h2(v[14], v[15]);
        g_hmT[idx] = p;
    }
    // PDL: signal the dependent sample_kernel once this CTA's stores are done.
    cudaTriggerProgrammaticLaunchCompletion();
}

// ---------------------------------------------------------------------------
// 256-bit read-only global load (Blackwell LDG.E.256): one full pixel.
// ---------------------------------------------------------------------------
static __device__ __forceinline__ void ldg256(const Pix* p, float (&f)[8]) {
    asm volatile(
        "ld.global.nc.v8.f32 {%0,%1,%2,%3,%4,%5,%6,%7}, [%8];"
        : "=f"(f[0]), "=f"(f[1]), "=f"(f[2]), "=f"(f[3]),
          "=f"(f[4]), "=f"(f[5]), "=f"(f[6]), "=f"(f[7])
        : "l"(p));
}

// Scalar unpack + FMA (proven fastest datapath).
static __device__ __forceinline__ void acc_corner(float (&acc)[16],
                                                  const float (&f)[8], float w) {
#pragma unroll
    for (int i = 0; i < 8; ++i) {
        __half2 h = *reinterpret_cast<const __half2*>(&f[i]);
        float2 u = __half22float2(h);
        acc[2 * i + 0] = fmaf(w, u.x, acc[2 * i + 0]);
        acc[2 * i + 1] = fmaf(w, u.y, acc[2 * i + 1]);
    }
}

// ---------------------------------------------------------------------------
// Kernel 2: gather, lane-paired + 2-view software pipeline.
// TWO threads per (b, n): lane parity jl handles column x0+jl (contiguous
// 64B pair shares L1 wavefronts within one LDG.256). The view loop is
// double-buffered: view v+1's two loads are issued BEFORE view v's
// accumulate, raising in-flight loads per thread from 2 to ~4.
// Reduction: keep-half butterfly (8 shfl); lane0 owns joints 0-7,
// lane1 owns joints 8-14.
// ---------------------------------------------------------------------------
__global__ void __launch_bounds__(256, 4) sample_kernel(const float* __restrict__ grid,
                                                        float* __restrict__ out) {
    const int tid = blockIdx.x * blockDim.x + threadIdx.x;  // 0 .. 2*B*NPTS-1
    const int pid = tid >> 1;        // point id
    const int jl  = tid & 1;         // lane role: 0 -> x0 column, 1 -> x1 column
    const int b   = pid / NPTS;
    const int n   = pid - b * NPTS;

    // PDL prologue: grid coords do NOT depend on the transpose — load them
    // before the dependency sync so these LDGs overlap the transpose kernel.
    const float2* g2 = reinterpret_cast<const float2*>(grid);
    float2 g[Vc];
#pragma unroll
    for (int v = 0; v < Vc; ++v)
        g[v] = g2[(size_t)(b * Vc + v) * NPTS + n];

    cudaGridDependencySynchronize();

    const Pix* hbase = g_hmT + (size_t)b * Vc * HW;

    // Compute this lane's two corner addresses + weights for view v.
    auto prep = [&](int v, const Pix*& q0, const Pix*& q1,
                    float& w0, float& w1) {
        const float ix = (g[v].x + 1.0f) * 0.5f * (float)(Wc - 1);
        const float iy = (g[v].y + 1.0f) * 0.5f * (float)(Hc - 1);
        const float x0f = floorf(ix);
        const float y0f = floorf(iy);
        const float wx1 = ix - x0f;
        const float wy1 = iy - y0f;

        int x0 = (int)x0f;
        int y0 = (int)y0f;
        x0 = max(0, min(x0, Wc - 1));
        y0 = max(0, min(y0, Hc - 1));
        const int xc = min(x0 + jl, Wc - 1);   // this lane's column
        const int y1 = min(y0 + 1, Hc - 1);

        const float wx = jl ? wx1 : (1.0f - wx1);
        w0 = wx * (1.0f - wy1);
        w1 = wx * wy1;

        const Pix* base = hbase + (size_t)v * HW;
        q0 = base + (size_t)y0 * Wc + xc;
        q1 = base + (size_t)y1 * Wc + xc;
    };

    float acc[16];
#pragma unroll
    for (int i = 0; i < 16; ++i) acc[i] = 0.0f;

    // Double-buffered pipeline over views.
    float f0[2][8], f1[2][8];
    float w0v[2], w1v[2];
    {
        const Pix *q0, *q1;
        prep(0, q0, q1, w0v[0], w1v[0]);
        ldg256(q0, f0[0]);
        ldg256(q1, f1[0]);
    }
#pragma unroll
    for (int v = 1; v < Vc; ++v) {
        const int cur = v & 1, prv = cur ^ 1;
        const Pix *q0, *q1;
        prep(v, q0, q1, w0v[cur], w1v[cur]);
        ldg256(q0, f0[cur]);                 // issue view v loads ...
        ldg256(q1, f1[cur]);
        acc_corner(acc, f0[prv], w0v[prv]);  // ... while consuming view v-1
        acc_corner(acc, f1[prv], w1v[prv]);
    }
    {
        const int last = (Vc - 1) & 1;       // view 4 lives in parity 0
        acc_corner(acc, f0[last], w0v[last]);
        acc_corner(acc, f1[last], w1v[last]);
    }

    // Keep-half butterfly: lane jl keeps joints [jl*8, jl*8+8).
    float r[8];
#pragma unroll
    for (int i = 0; i < 8; ++i) {
        const float send = jl ? acc[i] : acc[i + 8];
        const float keep = jl ? acc[i + 8] : acc[i];
        r[i] = keep + __shfl_xor_sync(0xffffffffu, send, 1);
    }

    const int jbase = jl * 8;
    const float s = 1.0f / (float)Vc;
    float* op = out + (size_t)b * Jc * NPTS + n;
#pragma unroll
    for (int k = 0; k < 8; ++k) {
        if (jbase + k < Jc) {
            float val = r[k] * s;
            val = fminf(fmaxf(val, 0.0f), 1.0f);
            op[(size_t)(jbase + k) * NPTS] = val;
        }
    }
}

// ---------------------------------------------------------------------------
extern "C" void kernel_launch(void* const* d_in, const int* in_sizes, int n_in,
                              void* d_out, int out_size) {
    const float* heatmaps = (const float*)d_in[0];  // (4,5,15,128,240) f32
    const float* grid     = (const float*)d_in[1];  // (4,5,1,128000,2) f32
    float* out            = (float*)d_out;          // (4,15,80,80,20) f32

    (void)in_sizes; (void)n_in; (void)out_size;

    const int tp_total = Bc * Vc * HW;              // 614400
    transpose_kernel<<<(tp_total + 255) / 256, 256>>>(heatmaps);

    // Sample kernel as a programmatic dependent launch: its grid-load
    // prologue overlaps the transpose; cudaGridDependencySynchronize()
    // inside the kernel enforces ordering before g_hmT is read.
    const int total = Bc * NPTS * 2;                // 1,024,000
    cudaLaunchConfig_t cfg = {};
    cfg.gridDim  = dim3((total + 255) / 256);
    cfg.blockDim = dim3(256);
    cfg.dynamicSmemBytes = 0;
    cudaLaunchAttribute attr[1];
    attr[0].id = cudaLaunchAttributeProgrammaticStreamSerialization;
    attr[0].val.programmaticStreamSerializationAllowed = 1;
    cfg.attrs = attr;
    cfg.numAttrs = 1;
    cudaLaunchKernelEx(&cfg, sample_kernel, grid, out);
}